// round 5
// baseline (speedup 1.0000x reference)
#include <cuda_runtime.h>

#define FULL 0xffffffffu
#define BATCH 32768
#define EPW 4           // elements per warp: one sincos round of 4

// out_i = K_i * sum_{T subset comp(A_i)} D_i[T] * prod_{b in T} sigma_b
//   sigma_b = sin(z_{7-b}),  K_i = prod_{b in A_i} cos(z_{7-b})
//   D_i[T]  = (1/256) sum_w (-1)^{popc(T&w)} cos(phi_w - phi_{w^A_i})  (weights only)
// A = {0x80,0x40,0xA0,0x50,0xA8,0x54,0xAA,0x55} (validated R1-R4).

__device__ float g_D[8][256];

// 1 block, 8 warps, warp i builds table i. No barriers: register+shuffle FWHT.
__global__ __launch_bounds__(256) void precompute_D(const float* __restrict__ weights) {
    const int i    = threadIdx.x >> 5;
    const int lane = threadIdx.x & 31;

    // A[i]: 0x80,0x40,0xA0,0x50,0xA8,0x54,0xAA,0x55
    const int sh = 6 - 2 * (i >> 1);
    const int A  = (((0xAA >> sh) << sh) >> (i & 1));

    const int msk[16]  = {0x01,0x03,0x06,0x0C,0x18,0x30,0x60,0xC0,
                          0x01,0x02,0x05,0x0A,0x14,0x28,0x50,0xA0};
    const int widx[16] = {7,6,5,4,3,2,1,0, 15,14,13,12,11,10,9,8};

    // lane holds w = r*32 + lane for r = 0..7
    float C[8];
#pragma unroll
    for (int r = 0; r < 8; r++) {
        const int w = r * 32 + lane;
        float d = 0.0f;
#pragma unroll
        for (int j = 0; j < 16; j++) {
            if (__popc(msk[j] & A) & 1) {              // A warp-uniform
                float th = weights[widx[j]];
                d += (__popc(msk[j] & w) & 1) ? -th : th;
            }
        }
        C[r] = __cosf(d);
    }

    // FWHT over r-bits (w bits 5..7): register butterflies
#pragma unroll
    for (int sb = 1; sb < 8; sb <<= 1) {
        float t[8];
#pragma unroll
        for (int r = 0; r < 8; r++)
            t[r] = (r & sb) ? (C[r ^ sb] - C[r]) : (C[r] + C[r ^ sb]);
#pragma unroll
        for (int r = 0; r < 8; r++) C[r] = t[r];
    }
    // FWHT over lane-bits (w bits 0..4): shuffle butterflies
#pragma unroll
    for (int s = 1; s < 32; s <<= 1) {
        float sign = (lane & s) ? -1.0f : 1.0f;
#pragma unroll
        for (int r = 0; r < 8; r++) {
            float o = __shfl_xor_sync(FULL, C[r], s);
            C[r] = fmaf(sign, C[r], o);
        }
    }

#pragma unroll
    for (int r = 0; r < 8; r++) {
        const int w = r * 32 + lane;
        g_D[i][w] = (w & A) ? 0.0f : C[r] * (1.0f / 256.0f);
    }
}

__global__ __launch_bounds__(128) void vqc_sparse(const float* __restrict__ inputs,
                                                  float* __restrict__ out) {
    const int lane = threadIdx.x & 31;
    const int warp = (blockIdx.x * blockDim.x + threadIdx.x) >> 5;

    const bool l0 = lane & 1, l1 = lane & 2, l2 = lane & 4, l3 = lane & 8, l4 = lane & 16;

    // ---- 15 (+1 masked) coefficients per lane (validated R4 mapping) ----
    float c0[4], c1[4], c2[2], c3[2], c4, c5, c6m, c7m;
#pragma unroll
    for (int j = 0; j < 4; j++) c0[j] = g_D[0][lane + 32 * j];
#pragma unroll
    for (int j = 0; j < 4; j++) c1[j] = g_D[1][lane + 32 * (j & 1) + 128 * (j >> 1)];
    c2[0] = g_D[2][lane];
    c2[1] = g_D[2][lane + 64];
    {
        int b3 = (lane & 15) + ((lane >> 4) & 1) * 32;
        c3[0] = g_D[3][b3];
        c3[1] = g_D[3][b3 + 128];
    }
    c4 = g_D[4][(lane & 7) + ((lane >> 3) & 1) * 16 + ((lane >> 4) & 1) * 64];
    c5 = g_D[5][(lane & 3) + ((lane >> 2) & 1) * 8 + ((lane >> 3) & 1) * 32 + ((lane >> 4) & 1) * 128];
    {
        int t6 = (lane & 1) + ((lane >> 1) & 1) * 4 + ((lane >> 2) & 1) * 16 + ((lane >> 3) & 1) * 64;
        c6m = l4 ? 0.0f : g_D[6][t6];
        c7m = l4 ? g_D[7][t6 << 1] : 0.0f;
    }

    const int i_out = (lane >> 2) & 7;   // output this lane writes (if lane&3==0)
    const int par = i_out & 1;
    const int rep = i_out >> 1;

    const int ebase = warp * EPW;
    // 4 elements x 8 qubits; thread holds qubit (lane&7) of element (lane>>3)
    float z = inputs[ebase * 8 + lane];
    float sz, cz;
    __sincosf(z, &sz, &cz);

#pragma unroll
    for (int e4 = 0; e4 < 4; e4++) {
        const int eoff = e4 * 8;

        // sigma_b = sin(z_{7-b})
        float sg[8];
#pragma unroll
        for (int b = 0; b < 8; b++) sg[b] = __shfl_sync(FULL, sz, eoff + 7 - b);

        // K_i (gathered cosines; only writer lanes consume)
        float k0 = __shfl_sync(FULL, cz, eoff + par);
        float k1 = __shfl_sync(FULL, cz, eoff + par + 2);
        float k2 = __shfl_sync(FULL, cz, eoff + par + 4);
        float k3 = __shfl_sync(FULL, cz, eoff + par + 6);
        float K = k0;
        if (rep >= 1) K *= k1;
        if (rep >= 2) K *= k2;
        if (rep >= 3) K *= k3;

        // shared predicated-product chain
        float S2 = l0 ? sg[0] : 1.0f;
        if (l1) S2 *= sg[1];
        float R3 = S2;  if (l2) R3 *= sg[2];
        float Q4 = R3;  if (l3) Q4 *= sg[3];
        float PA = Q4;  if (l4) PA *= sg[4];               // outs 0,1,2
        float PB = Q4;  if (l4) PB *= sg[5];               // out 3
        float PC = R3;  if (l3) PC *= sg[4];
        if (l4) PC *= sg[6];                               // out 4
        float PD = S2;  if (l2) PD *= sg[3];
        if (l3) PD *= sg[5];
        if (l4) PD *= sg[7];                               // out 5
        float t0 = l4 ? sg[1] : sg[0];
        float t1 = l4 ? sg[3] : sg[2];
        float t2 = l4 ? sg[5] : sg[4];
        float t3 = l4 ? sg[7] : sg[6];
        float PEF = l0 ? t0 : 1.0f;                        // out 6/7
        if (l1) PEF *= t1;
        if (l2) PEF *= t2;
        if (l3) PEF *= t3;

        float a[8];
        {
            float u = fmaf(c0[1], sg[5], c0[0]);
            float v = fmaf(c0[3], sg[5], c0[2]);
            a[0] = PA * fmaf(sg[6], v, u);
        }
        {
            float u = fmaf(c1[1], sg[5], c1[0]);
            float v = fmaf(c1[3], sg[5], c1[2]);
            a[1] = PA * fmaf(sg[7], v, u);
        }
        a[2] = PA * fmaf(c2[1], sg[6], c2[0]);
        a[3] = PB * fmaf(c3[1], sg[7], c3[0]);
        a[4] = PC * c4;
        a[5] = PD * c5;
        a[6] = PEF * c6m;
        a[7] = PEF * c7m;

        // multi-accumulator fold reduction (validated R2-R4)
#pragma unroll
        for (int j = 0; j < 4; j++) {
            float send = l4 ? a[j] : a[j + 4];
            float recv = __shfl_xor_sync(FULL, send, 16);
            a[j] = (l4 ? a[j + 4] : a[j]) + recv;
        }
#pragma unroll
        for (int j = 0; j < 2; j++) {
            float send = l3 ? a[j] : a[j + 2];
            float recv = __shfl_xor_sync(FULL, send, 8);
            a[j] = (l3 ? a[j + 2] : a[j]) + recv;
        }
        {
            float send = l2 ? a[0] : a[1];
            float recv = __shfl_xor_sync(FULL, send, 4);
            a[0] = (l2 ? a[1] : a[0]) + recv;
        }
        a[0] += __shfl_xor_sync(FULL, a[0], 2);
        a[0] += __shfl_xor_sync(FULL, a[0], 1);

        if ((lane & 3) == 0)
            out[(ebase + e4) * 8 + i_out] = K * a[0];
    }
}

extern "C" void kernel_launch(void* const* d_in, const int* in_sizes, int n_in,
                              void* d_out, int out_size) {
    const float* inputs  = (const float*)d_in[0];   // (32768, 8) float32
    const float* weights = (const float*)d_in[1];   // (2, 8)     float32
    float* out = (float*)d_out;                     // (32768, 8) float32

    precompute_D<<<1, 256>>>(weights);

    // 32768/4 = 8192 warps, 128-thread blocks -> 2048 blocks (exact fit)
    vqc_sparse<<<2048, 128>>>(inputs, out);
}

// round 6
// speedup vs baseline: 1.2764x; 1.2764x over previous
#include <cuda_runtime.h>

#define FULL 0xffffffffu
#define BATCH 32768

// out_i = K_i * sum_T D_i[T] * sigma_T,  sigma_T = prod_{b in T} sin z_{7-b},
// K_i = prod_{b in A_i} cos z_{7-b},  D from weight-only FWHT (validated R2-R5).
// A = {0x80,0x40,0xA0,0x50,0xA8,0x54,0xAA,0x55}.
// True supports (derived from even-subset XORs of S_i, intersected with T&A==0):
//   out0: {0x00,0x60}
//   out1: {0x00,0xA0,0x30,0x90}
//   out2: {0x00,0x50,0x18,0x48}
//   out3: {0x00,0x28,0x0C,0x24,0xA0,0x84,0xAC,0x88}
//   out4..7: full comp-lattices of A (32,32,16,16 entries).
// Bit b of T <-> qubit 7-b  =>  sigma factor for bit b is sz[7-b].

__device__ float g_D[8][256];

__device__ const unsigned char g_sp_i[18] = {0,0, 1,1,1,1, 2,2,2,2, 3,3,3,3,3,3,3,3};
__device__ const unsigned char g_sp_T[18] = {0x00,0x60, 0x00,0xA0,0x30,0x90, 0x00,0x50,0x18,0x48,
                                             0x00,0x28,0x0C,0x24,0xA0,0x84,0xAC,0x88};

// 8 blocks, 1 warp each; block i builds table i. No barriers (warp FWHT, validated R5).
__global__ __launch_bounds__(32) void precompute_D(const float* __restrict__ weights) {
    const int i    = blockIdx.x;
    const int lane = threadIdx.x;

    const int sh = 6 - 2 * (i >> 1);
    const int A  = (((0xAA >> sh) << sh) >> (i & 1));

    const int msk[16]  = {0x01,0x03,0x06,0x0C,0x18,0x30,0x60,0xC0,
                          0x01,0x02,0x05,0x0A,0x14,0x28,0x50,0xA0};
    const int widx[16] = {7,6,5,4,3,2,1,0, 15,14,13,12,11,10,9,8};

    float C[8];
#pragma unroll
    for (int r = 0; r < 8; r++) {
        const int w = r * 32 + lane;
        float d = 0.0f;
#pragma unroll
        for (int j = 0; j < 16; j++) {
            if (__popc(msk[j] & A) & 1) {
                float th = weights[widx[j]];
                d += (__popc(msk[j] & w) & 1) ? -th : th;
            }
        }
        C[r] = __cosf(d);
    }
    // FWHT over w bits 5..7 (register butterflies)
#pragma unroll
    for (int sb = 1; sb < 8; sb <<= 1) {
        float t[8];
#pragma unroll
        for (int r = 0; r < 8; r++)
            t[r] = (r & sb) ? (C[r ^ sb] - C[r]) : (C[r] + C[r ^ sb]);
#pragma unroll
        for (int r = 0; r < 8; r++) C[r] = t[r];
    }
    // FWHT over w bits 0..4 (shuffle butterflies)
#pragma unroll
    for (int s = 1; s < 32; s <<= 1) {
        float sign = (lane & s) ? -1.0f : 1.0f;
#pragma unroll
        for (int r = 0; r < 8; r++) {
            float o = __shfl_xor_sync(FULL, C[r], s);
            C[r] = fmaf(sign, C[r], o);
        }
    }
#pragma unroll
    for (int r = 0; r < 8; r++)
        g_D[i][r * 32 + lane] = C[r] * (1.0f / 256.0f);
}

__global__ __launch_bounds__(128) void vqc_eval(const float* __restrict__ inputs,
                                                float* __restrict__ out) {
    __shared__ float  sC[20];
    __shared__ float4 sD4[8], sD5[8];
    __shared__ float2 sD6[8], sD7[8];

    const int tid = threadIdx.x;
    // stage compacted coefficients (uniform per block)
    if (tid < 18) {
        sC[tid] = g_D[g_sp_i[tid]][g_sp_T[tid]];
    } else if (tid >= 32 && tid < 64) {            // d4: comp(0xA8) bits {0,1,2,4,6}
        int j = tid - 32;
        int T = (j & 7) | ((j & 8) << 1) | ((j & 16) << 2);
        ((float*)sD4)[j] = g_D[4][T];
    } else if (tid >= 64 && tid < 96) {            // d5: comp(0x54) bits {0,1,3,5,7}
        int j = tid - 64;
        int T = (j & 3) | ((j & 4) << 1) | ((j & 8) << 2) | ((j & 16) << 3);
        ((float*)sD5)[j] = g_D[5][T];
    } else if (tid >= 96 && tid < 112) {           // d6: comp(0xAA) bits {0,2,4,6}
        int j = tid - 96;
        int T = (j & 1) | ((j & 2) << 1) | ((j & 4) << 2) | ((j & 8) << 3);
        ((float*)sD6)[j] = g_D[6][T];
    } else if (tid >= 112 && tid < 128) {          // d7: comp(0x55) bits {1,3,5,7}
        int j = tid - 112;
        int T = ((j & 1) << 1) | ((j & 2) << 2) | ((j & 4) << 3) | ((j & 8) << 4);
        ((float*)sD7)[j] = g_D[7][T];
    }
    __syncthreads();

    const int e = blockIdx.x * 128 + tid;
    const float4 z0 = *reinterpret_cast<const float4*>(inputs + e * 8);
    const float4 z1 = *reinterpret_cast<const float4*>(inputs + e * 8 + 4);

    float sz0, cz0, sz1, cz1, sz2, cz2, sz3, cz3, sz4, cz4, sz5, cz5, sz6, cz6, sz7, cz7;
    __sincosf(z0.x, &sz0, &cz0);  __sincosf(z0.y, &sz1, &cz1);
    __sincosf(z0.z, &sz2, &cz2);  __sincosf(z0.w, &sz3, &cz3);
    __sincosf(z1.x, &sz4, &cz4);  __sincosf(z1.y, &sz5, &cz5);
    __sincosf(z1.z, &sz6, &cz6);  __sincosf(z1.w, &sz7, &cz7);

    // K_i = prod over A_i bits (bit b -> cz[7-b])
    float K0 = cz0,       K1 = cz1;
    float K2 = cz0 * cz2, K3 = cz1 * cz3;
    float K4 = K2 * cz4,  K5 = K3 * cz5;
    float K6 = K4 * cz6,  K7 = K5 * cz7;

    // shared pair products
    float s42 = sz4 * sz2, s40 = sz4 * sz0, s20 = sz2 * sz0, s420 = s42 * sz0;
    float m53 = sz5 * sz3, m51 = sz5 * sz1, m31 = sz3 * sz1, m531 = m53 * sz1;

    // ---- sparse outputs 0..3 ----
    float o0 = K0 * fmaf(sC[1], sz2 * sz1, sC[0]);
    float sA0 = s20;                                   // sigma(0xA0) = sz2*sz0
    float o1 = fmaf(sC[3], sA0, sC[2]);
    o1 = fmaf(sC[4], sz3 * sz2, o1);
    o1 = fmaf(sC[5], sz3 * sz0, o1);
    o1 *= K1;
    float o2 = fmaf(sC[7], m31, sC[6]);                // sigma(0x50) = sz3*sz1
    o2 = fmaf(sC[8], sz4 * sz3, o2);
    o2 = fmaf(sC[9], sz4 * sz1, o2);
    o2 *= K2;
    float s0C = sz5 * sz4;
    float o3 = fmaf(sC[11], s42, sC[10]);              // sigma(0x28) = sz4*sz2
    o3 = fmaf(sC[12], s0C, o3);
    o3 = fmaf(sC[13], sz5 * sz2, o3);
    o3 = fmaf(sC[14], sA0, o3);
    o3 = fmaf(sC[15], sz5 * sz0, o3);
    o3 = fmaf(sC[16], s0C * s20, o3);                  // sigma(0xAC)
    o3 = fmaf(sC[17], s40, o3);                        // sigma(0x88)
    o3 *= K3;

    // ---- dense walks: p tables (compile-time indexed after unroll) ----
    float p8[8] = {1.0f, sz4, sz2, s42, sz0, s40, s20, s420};  // out5 & out7
    float p6[8] = {1.0f, sz5, sz3, m53, sz1, m51, m31, m531};  // out6
    float p4[4] = {1.0f, sz3, sz1, m31};                       // out4 outer

    // out4: inner bits -> sz7, sz6, sz5; outer -> sz3, sz1
    float acc4 = 0.0f;
#pragma unroll
    for (int g = 0; g < 4; g++) {
        float4 a = sD4[2 * g], b = sD4[2 * g + 1];
        float lo = fmaf(a.y, sz7, a.x) + sz6 * fmaf(a.w, sz7, a.z);
        float hi = fmaf(b.y, sz7, b.x) + sz6 * fmaf(b.w, sz7, b.z);
        acc4 = fmaf(p4[g], fmaf(sz5, hi, lo), acc4);
    }
    // out5: inner bits -> sz7, sz6; outer -> sz4, sz2, sz0
    float acc5 = 0.0f;
#pragma unroll
    for (int g = 0; g < 8; g++) {
        float4 a = sD5[g];
        float inner = fmaf(a.y, sz7, a.x) + sz6 * fmaf(a.w, sz7, a.z);
        acc5 = fmaf(p8[g], inner, acc5);
    }
    // out6: inner bit -> sz7; outer -> sz5, sz3, sz1
    float acc6 = 0.0f;
#pragma unroll
    for (int g = 0; g < 8; g++) {
        float2 a = sD6[g];
        acc6 = fmaf(p6[g], fmaf(a.y, sz7, a.x), acc6);
    }
    // out7: inner bit -> sz6; outer -> sz4, sz2, sz0
    float acc7 = 0.0f;
#pragma unroll
    for (int g = 0; g < 8; g++) {
        float2 a = sD7[g];
        acc7 = fmaf(p8[g], fmaf(a.y, sz6, a.x), acc7);
    }

    float4 r0 = make_float4(o0, o1, o2, o3);
    float4 r1 = make_float4(K4 * acc4, K5 * acc5, K6 * acc6, K7 * acc7);
    *reinterpret_cast<float4*>(out + e * 8)     = r0;
    *reinterpret_cast<float4*>(out + e * 8 + 4) = r1;
}

extern "C" void kernel_launch(void* const* d_in, const int* in_sizes, int n_in,
                              void* d_out, int out_size) {
    const float* inputs  = (const float*)d_in[0];   // (32768, 8) float32
    const float* weights = (const float*)d_in[1];   // (2, 8)     float32
    float* out = (float*)d_out;                     // (32768, 8) float32

    precompute_D<<<8, 32>>>(weights);
    vqc_eval<<<BATCH / 128, 128>>>(inputs, out);    // 256 blocks, 1 thread/element
}

// round 7
// speedup vs baseline: 1.6057x; 1.2581x over previous
#include <cuda_runtime.h>

#define FULL 0xffffffffu
#define BATCH 32768

// Fully fused VQC: out_i = K_i * sum_T D_i[T] * sigma_T
//   sigma_T = prod_{b in T} sin z_{7-b},  K_i = prod_{b in A_i} cos z_{7-b}
//   D_i = (1/256) * FWHT_w[ cos(phi_w - phi_{w^A_i}) ]   (weights only)
// A = {0x80,0x40,0xA0,0x50,0xA8,0x54,0xAA,0x55}  (validated R1-R6).
// Each block: warp i recomputes table D_i into shared (barrier-free warp FWHT,
// validated R5/R6), one sync, then 1 thread = 1 batch element, reading
// coefficients at compile-time offsets (support maps validated R6).

__global__ __launch_bounds__(256) void vqc_fused(const float* __restrict__ inputs,
                                                 const float* __restrict__ weights,
                                                 float* __restrict__ out) {
    __shared__ float sD[8][256];

    const int tid  = threadIdx.x;
    const int lane = tid & 31;
    const int wid  = tid >> 5;
    const int e    = blockIdx.x * 256 + tid;

    // ---- hoisted input load + sincos (overlaps FWHT below) ----
    const float4 z0 = *reinterpret_cast<const float4*>(inputs + e * 8);
    const float4 z1 = *reinterpret_cast<const float4*>(inputs + e * 8 + 4);
    float sz0, cz0, sz1, cz1, sz2, cz2, sz3, cz3, sz4, cz4, sz5, cz5, sz6, cz6, sz7, cz7;
    __sincosf(z0.x, &sz0, &cz0);  __sincosf(z0.y, &sz1, &cz1);
    __sincosf(z0.z, &sz2, &cz2);  __sincosf(z0.w, &sz3, &cz3);
    __sincosf(z1.x, &sz4, &cz4);  __sincosf(z1.y, &sz5, &cz5);
    __sincosf(z1.z, &sz6, &cz6);  __sincosf(z1.w, &sz7, &cz7);

    // ---- per-warp FWHT: warp `wid` builds table D_wid ----
    {
        const int i  = wid;
        const int sh = 6 - 2 * (i >> 1);
        const int A  = (((0xAA >> sh) << sh) >> (i & 1));

        const int msk[16]  = {0x01,0x03,0x06,0x0C,0x18,0x30,0x60,0xC0,
                              0x01,0x02,0x05,0x0A,0x14,0x28,0x50,0xA0};
        const int widx[16] = {7,6,5,4,3,2,1,0, 15,14,13,12,11,10,9,8};

        float C[8];
#pragma unroll
        for (int r = 0; r < 8; r++) {
            const int w = r * 32 + lane;
            float d = 0.0f;
#pragma unroll
            for (int j = 0; j < 16; j++) {
                if (__popc(msk[j] & A) & 1) {                // warp-uniform predicate
                    float th = __ldg(&weights[widx[j]]);
                    d += (__popc(msk[j] & w) & 1) ? -th : th;
                }
            }
            C[r] = __cosf(d);
        }
        // FWHT over w bits 5..7 (register butterflies)
#pragma unroll
        for (int sb = 1; sb < 8; sb <<= 1) {
            float t[8];
#pragma unroll
            for (int r = 0; r < 8; r++)
                t[r] = (r & sb) ? (C[r ^ sb] - C[r]) : (C[r] + C[r ^ sb]);
#pragma unroll
            for (int r = 0; r < 8; r++) C[r] = t[r];
        }
        // FWHT over w bits 0..4 (shuffle butterflies)
#pragma unroll
        for (int s = 1; s < 32; s <<= 1) {
            float sign = (lane & s) ? -1.0f : 1.0f;
#pragma unroll
            for (int r = 0; r < 8; r++) {
                float o = __shfl_xor_sync(FULL, C[r], s);
                C[r] = fmaf(sign, C[r], o);
            }
        }
#pragma unroll
        for (int r = 0; r < 8; r++)
            sD[i][r * 32 + lane] = C[r] * (1.0f / 256.0f);
    }
    __syncthreads();

    // ---- evaluation (1 thread = 1 element), coefficients at constant offsets ----
    // K_i = prod over A_i bits (bit b -> cz[7-b])
    float K0 = cz0,       K1 = cz1;
    float K2 = cz0 * cz2, K3 = cz1 * cz3;
    float K4 = K2 * cz4,  K5 = K3 * cz5;
    float K6 = K4 * cz6,  K7 = K5 * cz7;

    float s42 = sz4 * sz2, s40 = sz4 * sz0, s20 = sz2 * sz0, s420 = s42 * sz0;
    float m53 = sz5 * sz3, m51 = sz5 * sz1, m31 = sz3 * sz1, m531 = m53 * sz1;

    // sparse outputs 0..3 (supports validated R6)
    float o0 = K0 * fmaf(sD[0][0x60], sz2 * sz1, sD[0][0x00]);

    float o1 = fmaf(sD[1][0xA0], s20, sD[1][0x00]);
    o1 = fmaf(sD[1][0x30], sz3 * sz2, o1);
    o1 = fmaf(sD[1][0x90], sz3 * sz0, o1);
    o1 *= K1;

    float o2 = fmaf(sD[2][0x50], m31, sD[2][0x00]);
    o2 = fmaf(sD[2][0x18], sz4 * sz3, o2);
    o2 = fmaf(sD[2][0x48], sz4 * sz1, o2);
    o2 *= K2;

    float s0C = sz5 * sz4;
    float o3 = fmaf(sD[3][0x28], s42, sD[3][0x00]);
    o3 = fmaf(sD[3][0x0C], s0C, o3);
    o3 = fmaf(sD[3][0x24], sz5 * sz2, o3);
    o3 = fmaf(sD[3][0xA0], s20, o3);
    o3 = fmaf(sD[3][0x84], sz5 * sz0, o3);
    o3 = fmaf(sD[3][0xAC], s0C * s20, o3);
    o3 = fmaf(sD[3][0x88], s40, o3);
    o3 *= K3;

    // dense walks (outer-monomial tables, compile-time indexed after unroll)
    float p8[8] = {1.0f, sz4, sz2, s42, sz0, s40, s20, s420};  // out5 & out7
    float p6[8] = {1.0f, sz5, sz3, m53, sz1, m51, m31, m531};  // out6
    float p4[4] = {1.0f, sz3, sz1, m31};                       // out4 outer

    // out4: comp(0xA8); inner sz7,sz6,sz5; float4 pairs at T bases {0,16,64,80}
    const int b4[4] = {0, 16, 64, 80};
    float acc4 = 0.0f;
#pragma unroll
    for (int g = 0; g < 4; g++) {
        float4 a = *reinterpret_cast<const float4*>(&sD[4][b4[g]]);
        float4 b = *reinterpret_cast<const float4*>(&sD[4][b4[g] + 4]);
        float lo = fmaf(a.y, sz7, a.x) + sz6 * fmaf(a.w, sz7, a.z);
        float hi = fmaf(b.y, sz7, b.x) + sz6 * fmaf(b.w, sz7, b.z);
        acc4 = fmaf(p4[g], fmaf(sz5, hi, lo), acc4);
    }
    // out5: comp(0x54); inner sz7,sz6; float4 at T bases {0,8,32,40,128,136,160,168}
    const int b5[8] = {0, 8, 32, 40, 128, 136, 160, 168};
    float acc5 = 0.0f;
#pragma unroll
    for (int g = 0; g < 8; g++) {
        float4 a = *reinterpret_cast<const float4*>(&sD[5][b5[g]]);
        float inner = fmaf(a.y, sz7, a.x) + sz6 * fmaf(a.w, sz7, a.z);
        acc5 = fmaf(p8[g], inner, acc5);
    }
    // out6: comp(0xAA); inner sz7; float2 at T bases {0,4,16,20,64,68,80,84}
    const int b6[8] = {0, 4, 16, 20, 64, 68, 80, 84};
    float acc6 = 0.0f;
#pragma unroll
    for (int g = 0; g < 8; g++) {
        float2 a = *reinterpret_cast<const float2*>(&sD[6][b6[g]]);
        acc6 = fmaf(p6[g], fmaf(a.y, sz7, a.x), acc6);
    }
    // out7: comp(0x55); inner sz6 (pairs T, T+2); T bases {0,8,32,40,128,136,160,168}
    float acc7 = 0.0f;
#pragma unroll
    for (int g = 0; g < 8; g++) {
        float lo = sD[7][b5[g]];
        float hi = sD[7][b5[g] + 2];
        acc7 = fmaf(p8[g], fmaf(hi, sz6, lo), acc7);
    }

    float4 r0 = make_float4(o0, o1, o2, o3);
    float4 r1 = make_float4(K4 * acc4, K5 * acc5, K6 * acc6, K7 * acc7);
    *reinterpret_cast<float4*>(out + e * 8)     = r0;
    *reinterpret_cast<float4*>(out + e * 8 + 4) = r1;
}

extern "C" void kernel_launch(void* const* d_in, const int* in_sizes, int n_in,
                              void* d_out, int out_size) {
    const float* inputs  = (const float*)d_in[0];   // (32768, 8) float32
    const float* weights = (const float*)d_in[1];   // (2, 8)     float32
    float* out = (float*)d_out;                     // (32768, 8) float32

    vqc_fused<<<BATCH / 256, 256>>>(inputs, weights, out);   // single launch
}